// round 15
// baseline (speedup 1.0000x reference)
#include <cuda_runtime.h>
#include <cuda_fp16.h>

#define BB 4
#define NN 512
#define DD 256

// ---------------- scratch (static device globals: allocation-free) ----------
__device__ __align__(16) __half g_q[BB * NN * DD];     // 1 MB
__device__ __align__(16) __half g_k[BB * NN * DD];     // 1 MB
__device__ __align__(16) float  g_wei[BB * NN * NN];   // 4 MB (raw scores)
__device__ __align__(16) __half g_weih[BB * NN * NN];  // 2 MB (softmaxed, fp16)
__device__ __align__(16) __half g_xh[BB * NN * DD];    // 1 MB (X in fp16)

// ---------------- small PTX helpers ------------------------------------------
__device__ __forceinline__ unsigned tanh_h2(unsigned xi) {
    unsigned yi;
    asm("tanh.approx.f16x2 %0, %1;" : "=r"(yi) : "r"(xi));
    return yi;
}
__device__ __forceinline__ unsigned hadd2_u(unsigned a, unsigned b) {
    unsigned c;
    asm("add.f16x2 %0, %1, %2;" : "=r"(c) : "r"(a), "r"(b));
    return c;
}
__device__ __forceinline__ unsigned hfma2_u(unsigned a, unsigned b, unsigned c) {
    unsigned d;
    asm("fma.rn.f16x2 %0, %1, %2, %3;" : "=r"(d) : "r"(a), "r"(b), "r"(c));
    return d;
}
__device__ __forceinline__ unsigned smem_u32(const void* p) {
    return (unsigned)__cvta_generic_to_shared(p);
}
__device__ __forceinline__ void cp16(void* dst, const void* src) {
    asm volatile("cp.async.cg.shared.global [%0], [%1], 16;"
        :: "r"(smem_u32(dst)), "l"(src));
}
#define CP_COMMIT() asm volatile("cp.async.commit_group;")
#define CP_WAIT0()  asm volatile("cp.async.wait_group 0;")

__device__ __forceinline__ void ldsm_x4(unsigned* r, const __half* p) {
    unsigned a = smem_u32(p);
    asm volatile("ldmatrix.sync.aligned.m8n8.x4.shared.b16 {%0,%1,%2,%3}, [%4];"
        : "=r"(r[0]), "=r"(r[1]), "=r"(r[2]), "=r"(r[3]) : "r"(a));
}
__device__ __forceinline__ void ldsm_x4_trans(unsigned* r, const __half* p) {
    unsigned a = smem_u32(p);
    asm volatile("ldmatrix.sync.aligned.m8n8.x4.trans.shared.b16 {%0,%1,%2,%3}, [%4];"
        : "=r"(r[0]), "=r"(r[1]), "=r"(r[2]), "=r"(r[3]) : "r"(a));
}
__device__ __forceinline__ void mma16816(float* c, const unsigned* a,
                                         unsigned b0, unsigned b1) {
    asm volatile("mma.sync.aligned.m16n8k16.row.col.f32.f16.f16.f32 "
        "{%0,%1,%2,%3}, {%4,%5,%6,%7}, {%8,%9}, {%0,%1,%2,%3};"
        : "+f"(c[0]), "+f"(c[1]), "+f"(c[2]), "+f"(c[3])
        : "r"(a[0]), "r"(a[1]), "r"(a[2]), "r"(a[3]), "r"(b0), "r"(b1));
}
__device__ __forceinline__ uint4 pack8f_to_h2x4(float4 a, float4 b) {
    __half2 h0 = __floats2half2_rn(a.x, a.y);
    __half2 h1 = __floats2half2_rn(a.z, a.w);
    __half2 h2 = __floats2half2_rn(b.x, b.y);
    __half2 h3 = __floats2half2_rn(b.z, b.w);
    uint4 u;
    u.x = *reinterpret_cast<unsigned*>(&h0);
    u.y = *reinterpret_cast<unsigned*>(&h1);
    u.z = *reinterpret_cast<unsigned*>(&h2);
    u.w = *reinterpret_cast<unsigned*>(&h3);
    return u;
}

// ---------------- kernel 1: q/k projections via HMMA, f32->f16 in-staging ----
// out[n][e] = sum_d X[n][d] * W[e][d] + bias[e], fp16 out. BM=128 BN=64 BK=32.
// Reads X/W in f32 (L2-resident), converts in registers, double-buffered smem.
// (z==0, x==0) blocks additionally emit converted A-tiles to g_xh (X in fp16).
__global__ __launch_bounds__(256) void proj_mma(
    const float* __restrict__ X,
    const float* __restrict__ Ww, const float* __restrict__ Wb,
    const float* __restrict__ Uw, const float* __restrict__ Ub)
{
    __shared__ __half As[2][128][40];   // 80B row stride (5x16B) ldsm-clean
    __shared__ __half Bs[2][64][40];

    const float* Wmat = blockIdx.z ? Uw : Ww;
    const float* bias = blockIdx.z ? Ub : Wb;
    __half*      out  = blockIdx.z ? g_k : g_q;
    const bool emit_x = (blockIdx.z == 0) && (blockIdx.x == 0);

    const int bn = blockIdx.x * 64;
    const int bm = blockIdx.y * 128;
    const int tid = threadIdx.x, warp = tid >> 5, lane = tid & 31;
    const int wm = warp >> 1, wn = warp & 1;   // warp tile 32x32
    const int gq = lane >> 2, tq = lane & 3;

    // staging coords: A 128 rows x (2 threads/row, 16 cols each); B 64 x (4x8)
    const int arow = tid >> 1, acol = (tid & 1) * 16;
    const int brow = tid >> 2, bcol = (tid & 3) * 8;

    float acc[2][4][4] = {};   // [tm16][tn8][4]
    float4 a4[4], b4[2];

    // prologue: load stage 0 (f32)
    {
        const float4* ap = (const float4*)&X[(bm + arow) * DD + acol];
        a4[0] = ap[0]; a4[1] = ap[1]; a4[2] = ap[2]; a4[3] = ap[3];
        const float4* bp = (const float4*)&Wmat[(bn + brow) * DD + bcol];
        b4[0] = bp[0]; b4[1] = bp[1];
    }

    #pragma unroll
    for (int it = 0; it < 8; it++) {
        const int s = it & 1;
        // convert + store staged regs to smem buffer s
        uint4 ua0 = pack8f_to_h2x4(a4[0], a4[1]);
        uint4 ua1 = pack8f_to_h2x4(a4[2], a4[3]);
        uint4 ub  = pack8f_to_h2x4(b4[0], b4[1]);
        *(uint4*)&As[s][arow][acol]     = ua0;
        *(uint4*)&As[s][arow][acol + 8] = ua1;
        *(uint4*)&Bs[s][brow][bcol]     = ub;
        if (emit_x) {
            __half* xp = &g_xh[(bm + arow) * DD + it * 32 + acol];
            *(uint4*)xp       = ua0;
            *(uint4*)(xp + 8) = ua1;
        }
        __syncthreads();

        if (it < 7) {   // prefetch next stage (overlaps MMA below)
            int nk = (it + 1) * 32;
            const float4* ap = (const float4*)&X[(bm + arow) * DD + nk + acol];
            a4[0] = ap[0]; a4[1] = ap[1]; a4[2] = ap[2]; a4[3] = ap[3];
            const float4* bp = (const float4*)&Wmat[(bn + brow) * DD + nk + bcol];
            b4[0] = bp[0]; b4[1] = bp[1];
        }

        #pragma unroll
        for (int ks = 0; ks < 2; ks++) {
            int kc = ks * 16;
            unsigned a[2][4], bf[2][4];
            #pragma unroll
            for (int tm = 0; tm < 2; tm++) {
                int r = wm * 32 + tm * 16 + (lane & 15);
                int c = kc + 8 * (lane >> 4);
                ldsm_x4(a[tm], &As[s][r][c]);
            }
            #pragma unroll
            for (int tn = 0; tn < 2; tn++) {
                int r = wn * 32 + tn * 16 + (lane & 7) + 8 * (lane >> 4);
                int c = kc + 8 * ((lane >> 3) & 1);
                ldsm_x4(bf[tn], &Bs[s][r][c]);
            }
            #pragma unroll
            for (int tm = 0; tm < 2; tm++)
                #pragma unroll
                for (int tn8 = 0; tn8 < 4; tn8++)
                    mma16816(acc[tm][tn8], a[tm],
                             bf[tn8 >> 1][(tn8 & 1) * 2],
                             bf[tn8 >> 1][(tn8 & 1) * 2 + 1]);
        }
    }

    #pragma unroll
    for (int tm = 0; tm < 2; tm++) {
        #pragma unroll
        for (int tn8 = 0; tn8 < 4; tn8++) {
            int c = bn + wn * 32 + tn8 * 8 + 2 * tq;
            float2 bv = *(const float2*)&bias[c];
            int r0 = bm + wm * 32 + tm * 16 + gq;
            __half2 h0 = __floats2half2_rn(acc[tm][tn8][0] + bv.x,
                                           acc[tm][tn8][1] + bv.y);
            __half2 h1 = __floats2half2_rn(acc[tm][tn8][2] + bv.x,
                                           acc[tm][tn8][3] + bv.y);
            *(__half2*)&out[r0 * DD + c] = h0;
            *(__half2*)&out[(r0 + 8) * DD + c] = h1;
        }
    }
}

// ---------------- kernel 2: additive-attention scores (R14 proven state) ----
#define KT 32
#define QB 64
#define QSTAGE 32

__global__ __launch_bounds__(256, 3) void score_kernel(const float* __restrict__ Va)
{
    __shared__ __align__(16) unsigned q_sh[QSTAGE][320];  // 40 KB

    const int tid  = threadIdx.x;
    const int w    = tid >> 5;
    const int lane = tid & 31;
    const int dg   = lane >> 2;
    const int kis  = lane & 3;

    const int b     = blockIdx.z;
    const int k0    = blockIdx.x * KT;
    const int qbase = blockIdx.y * QB;
    const int krow  = k0 + w * 4 + kis;

    unsigned kreg[16];
    {
        const uint4* kp = reinterpret_cast<const uint4*>(
            g_k + ((b * NN + krow) << 8) + dg * 32);
        #pragma unroll
        for (int j = 0; j < 4; j++) {
            uint4 t = kp[j];
            kreg[4*j+0] = t.x; kreg[4*j+1] = t.y;
            kreg[4*j+2] = t.z; kreg[4*j+3] = t.w;
        }
    }
    unsigned vh[16];
    {
        const float4* vp = reinterpret_cast<const float4*>(Va + dg * 32);
        #pragma unroll
        for (int j = 0; j < 8; j++) {
            float4 v = vp[j];
            __half2 a = __floats2half2_rn(v.x, v.y);
            __half2 c = __floats2half2_rn(v.z, v.w);
            vh[2*j]   = *reinterpret_cast<unsigned*>(&a);
            vh[2*j+1] = *reinterpret_cast<unsigned*>(&c);
        }
    }

    for (int qc = 0; qc < QB; qc += QSTAGE) {
        __syncthreads();
        const uint4* gq4 = reinterpret_cast<const uint4*>(
            g_q + ((b * NN + qbase + qc) << 8));
        #pragma unroll
        for (int l = 0; l < 4; l++) {
            int idx = tid + 256 * l;
            int r  = idx >> 5;
            int p4 = idx & 31;
            uint4 v = gq4[(r << 5) + p4];
            *reinterpret_cast<uint4*>(&q_sh[r][(p4 >> 2) * 40 + (p4 & 3) * 4]) = v;
        }
        __syncthreads();

        #pragma unroll 2
        for (int qi = 0; qi < QSTAGE; qi++) {
            const uint4* q4 = reinterpret_cast<const uint4*>(&q_sh[qi][dg * 40]);
            unsigned hacc[4] = {0u, 0u, 0u, 0u};
            #pragma unroll
            for (int j = 0; j < 4; j++) {
                uint4 qv = q4[j];
                unsigned qh[4] = {qv.x, qv.y, qv.z, qv.w};
                #pragma unroll
                for (int u = 0; u < 4; u++) {
                    int i = 4 * j + u;
                    unsigned t = tanh_h2(hadd2_u(qh[u], kreg[i]));
                    hacc[u] = hfma2_u(t, vh[i], hacc[u]);
                }
            }
            float2 f0 = __half22float2(*reinterpret_cast<__half2*>(&hacc[0]));
            float2 f1 = __half22float2(*reinterpret_cast<__half2*>(&hacc[1]));
            float2 f2 = __half22float2(*reinterpret_cast<__half2*>(&hacc[2]));
            float2 f3 = __half22float2(*reinterpret_cast<__half2*>(&hacc[3]));
            float partial = ((f0.x + f0.y) + (f1.x + f1.y))
                          + ((f2.x + f2.y) + (f3.x + f3.y));
            partial += __shfl_xor_sync(0xffffffffu, partial, 16);
            partial += __shfl_xor_sync(0xffffffffu, partial, 8);
            partial += __shfl_xor_sync(0xffffffffu, partial, 4);
            if (dg == 0) {
                g_wei[((b * NN + qbase + qc + qi) << 9) + krow] = partial;
            }
        }
    }
}

// ---------------- kernel 3: masked softmax -> fp16 weights (4 rows/block) ---
__global__ __launch_bounds__(512) void softmax_kernel(const int* __restrict__ mask)
{
    const int sub = threadIdx.x >> 7;          // row within block (0..3)
    const int t   = threadIdx.x & 127;
    const int row = blockIdx.x * 4 + sub;      // b*N + q
    const float* wrow = g_wei + row * NN;
    const int* mrow = mask + row * NN;
    __shared__ float red[4][4];

    float4 v = reinterpret_cast<const float4*>(wrow)[t];
    int4   m = reinterpret_cast<const int4*>(mrow)[t];
    if (m.x == 0) v.x = -1e30f;
    if (m.y == 0) v.y = -1e30f;
    if (m.z == 0) v.z = -1e30f;
    if (m.w == 0) v.w = -1e30f;

    float mx = fmaxf(fmaxf(v.x, v.y), fmaxf(v.z, v.w));
    #pragma unroll
    for (int s = 16; s > 0; s >>= 1) mx = fmaxf(mx, __shfl_xor_sync(0xffffffffu, mx, s));
    if ((t & 31) == 0) red[sub][t >> 5] = mx;
    __syncthreads();
    mx = fmaxf(fmaxf(red[sub][0], red[sub][1]), fmaxf(red[sub][2], red[sub][3]));
    __syncthreads();

    v.x = __expf(v.x - mx); v.y = __expf(v.y - mx);
    v.z = __expf(v.z - mx); v.w = __expf(v.w - mx);
    float sum = (v.x + v.y) + (v.z + v.w);
    #pragma unroll
    for (int s = 16; s > 0; s >>= 1) sum += __shfl_xor_sync(0xffffffffu, sum, s);
    if ((t & 31) == 0) red[sub][t >> 5] = sum;
    __syncthreads();
    sum = (red[sub][0] + red[sub][1]) + (red[sub][2] + red[sub][3]);
    float inv = 1.0f / sum;

    __half2 h01 = __floats2half2_rn(v.x * inv, v.y * inv);
    __half2 h23 = __floats2half2_rn(v.z * inv, v.w * inv);
    uint2 o;
    o.x = *reinterpret_cast<unsigned*>(&h01);
    o.y = *reinterpret_cast<unsigned*>(&h23);
    reinterpret_cast<uint2*>(g_weih + row * NN)[t] = o;
}

// ---------------- kernel 4: out = wei @ X via HMMA, cp.async pipelined -------
__global__ __launch_bounds__(256) void av_mma(float* __restrict__ out)
{
    __shared__ __half As[2][64][40];
    __shared__ __half Bs[2][32][72];

    const int b  = blockIdx.z;
    const int bn = blockIdx.x * 64;
    const int bm = blockIdx.y * 64;
    const __half* A  = g_weih + b * NN * NN;
    const __half* Bx = g_xh + b * NN * DD;

    const int tid = threadIdx.x, warp = tid >> 5, lane = tid & 31;
    const int wm = warp >> 2, wn = warp & 3;
    const int gq = lane >> 2, tq = lane & 3;

    const int ar = tid >> 2, aq = tid & 3;
    const int br = tid >> 3, bq = tid & 7;

    float acc[2][2][4] = {};

    cp16(&As[0][ar][aq * 8], &A[(bm + ar) * NN + aq * 8]);
    cp16(&Bs[0][br][bq * 8], &Bx[br * DD + bn + bq * 8]);
    CP_COMMIT();

    #pragma unroll 1
    for (int it = 0; it < 16; it++) {
        CP_WAIT0();
        __syncthreads();
        if (it < 15) {
            int nk = (it + 1) * 32, s = (it + 1) & 1;
            cp16(&As[s][ar][aq * 8], &A[(bm + ar) * NN + nk + aq * 8]);
            cp16(&Bs[s][br][bq * 8], &Bx[(nk + br) * DD + bn + bq * 8]);
            CP_COMMIT();
        }
        const int cur = it & 1;

        #pragma unroll
        for (int ks = 0; ks < 2; ks++) {
            int kc = ks * 16;
            unsigned a[2][4], bf[4];
            #pragma unroll
            for (int tm = 0; tm < 2; tm++) {
                int r = wm * 32 + tm * 16 + (lane & 15);
                int c = kc + 8 * (lane >> 4);
                ldsm_x4(a[tm], &As[cur][r][c]);
            }
            {
                int kr = kc + (lane & 7) + 8 * ((lane >> 3) & 1);
                int nc = wn * 16 + 8 * (lane >> 4);
                ldsm_x4_trans(bf, &Bs[cur][kr][nc]);
            }
            #pragma unroll
            for (int tm = 0; tm < 2; tm++)
                #pragma unroll
                for (int tn8 = 0; tn8 < 2; tn8++)
                    mma16816(acc[tm][tn8], a[tm], bf[tn8 * 2], bf[tn8 * 2 + 1]);
        }
    }

    #pragma unroll
    for (int tm = 0; tm < 2; tm++) {
        #pragma unroll
        for (int tn8 = 0; tn8 < 2; tn8++) {
            int c  = bn + wn * 16 + tn8 * 8 + 2 * tq;
            int r0 = bm + wm * 32 + tm * 16 + gq;
            *(float2*)&out[(b * NN + r0) * DD + c] =
                make_float2(acc[tm][tn8][0], acc[tm][tn8][1]);
            *(float2*)&out[(b * NN + r0 + 8) * DD + c] =
                make_float2(acc[tm][tn8][2], acc[tm][tn8][3]);
        }
    }
}

// ---------------- launcher ---------------------------------------------------
extern "C" void kernel_launch(void* const* d_in, const int* in_sizes, int n_in,
                              void* d_out, int out_size)
{
    const float* X    = (const float*)d_in[0];  // [4,512,256]
    const int*   mask = (const int*)  d_in[1];  // [4,512,512]
    const float* Wa_w = (const float*)d_in[2];  // [256,256]
    const float* Wa_b = (const float*)d_in[3];  // [256]
    const float* Ua_w = (const float*)d_in[4];  // [256,256]
    const float* Ua_b = (const float*)d_in[5];  // [256]
    const float* Va_w = (const float*)d_in[6];  // [1,256]
    // d_in[7] = Va_b : softmax-invariant constant -> unused

    (void)in_sizes; (void)n_in; (void)out_size;

    dim3 pgrid(DD / 64, (BB * NN) / 128, 2);    // 128 blocks (converts inline)
    proj_mma<<<pgrid, 256>>>(X, Wa_w, Wa_b, Ua_w, Ua_b);

    dim3 sgrid(NN / KT, NN / QB, BB);           // 512 blocks
    score_kernel<<<sgrid, 256>>>(Va_w);

    softmax_kernel<<<512, 512>>>(mask);

    dim3 agrid(DD / 64, NN / 64, BB);           // 128 blocks
    av_mma<<<agrid, 256>>>((float*)d_out);
}

// round 16
// speedup vs baseline: 1.0609x; 1.0609x over previous
#include <cuda_runtime.h>
#include <cuda_fp16.h>

#define BB 4
#define NN 512
#define DD 256

// ---------------- scratch (static device globals: allocation-free) ----------
__device__ __align__(16) __half g_q[BB * NN * DD];     // 1 MB
__device__ __align__(16) __half g_k[BB * NN * DD];     // 1 MB
__device__ __align__(16) float  g_wei[BB * NN * NN];   // 4 MB (raw scores)
__device__ __align__(16) __half g_weih[BB * NN * NN];  // 2 MB (softmaxed, fp16)
__device__ __align__(16) __half g_xh[BB * NN * DD];    // 1 MB (X in fp16)
__device__ __align__(16) __half g_wh[DD * DD];         // Wa_w fp16
__device__ __align__(16) __half g_uh[DD * DD];         // Ua_w fp16

// ---------------- small PTX helpers ------------------------------------------
__device__ __forceinline__ unsigned tanh_h2(unsigned xi) {
    unsigned yi;
    asm("tanh.approx.f16x2 %0, %1;" : "=r"(yi) : "r"(xi));
    return yi;
}
__device__ __forceinline__ unsigned hadd2_u(unsigned a, unsigned b) {
    unsigned c;
    asm("add.f16x2 %0, %1, %2;" : "=r"(c) : "r"(a), "r"(b));
    return c;
}
__device__ __forceinline__ unsigned hfma2_u(unsigned a, unsigned b, unsigned c) {
    unsigned d;
    asm("fma.rn.f16x2 %0, %1, %2, %3;" : "=r"(d) : "r"(a), "r"(b), "r"(c));
    return d;
}
__device__ __forceinline__ unsigned smem_u32(const void* p) {
    return (unsigned)__cvta_generic_to_shared(p);
}
__device__ __forceinline__ void cp16(void* dst, const void* src) {
    asm volatile("cp.async.cg.shared.global [%0], [%1], 16;"
        :: "r"(smem_u32(dst)), "l"(src));
}
#define CP_COMMIT() asm volatile("cp.async.commit_group;")
#define CP_WAIT0()  asm volatile("cp.async.wait_group 0;")
#define CP_WAIT1()  asm volatile("cp.async.wait_group 1;")

__device__ __forceinline__ void ldsm_x4(unsigned* r, const __half* p) {
    unsigned a = smem_u32(p);
    asm volatile("ldmatrix.sync.aligned.m8n8.x4.shared.b16 {%0,%1,%2,%3}, [%4];"
        : "=r"(r[0]), "=r"(r[1]), "=r"(r[2]), "=r"(r[3]) : "r"(a));
}
__device__ __forceinline__ void ldsm_x4_trans(unsigned* r, const __half* p) {
    unsigned a = smem_u32(p);
    asm volatile("ldmatrix.sync.aligned.m8n8.x4.trans.shared.b16 {%0,%1,%2,%3}, [%4];"
        : "=r"(r[0]), "=r"(r[1]), "=r"(r[2]), "=r"(r[3]) : "r"(a));
}
__device__ __forceinline__ void mma16816(float* c, const unsigned* a,
                                         unsigned b0, unsigned b1) {
    asm volatile("mma.sync.aligned.m16n8k16.row.col.f32.f16.f16.f32 "
        "{%0,%1,%2,%3}, {%4,%5,%6,%7}, {%8,%9}, {%0,%1,%2,%3};"
        : "+f"(c[0]), "+f"(c[1]), "+f"(c[2]), "+f"(c[3])
        : "r"(a[0]), "r"(a[1]), "r"(a[2]), "r"(a[3]), "r"(b0), "r"(b1));
}

// ---------------- kernel 0: fp32 -> fp16 conversions (R14 proven) -----------
// float4 units: X = 131072 f4; Wa_w = 16384 (cum 147456); Ua_w = 16384 (cum 163840)
__global__ __launch_bounds__(256) void conv_kernel(
    const float4* __restrict__ X4, const float4* __restrict__ Wa4,
    const float4* __restrict__ Ua4)
{
    int i = blockIdx.x * 256 + threadIdx.x;     // 0 .. 163839
    const float4* src;
    uint2* dst;
    int j;
    if (i < 131072)      { src = X4;  j = i;          dst = (uint2*)g_xh; }
    else if (i < 147456) { src = Wa4; j = i - 131072; dst = (uint2*)g_wh; }
    else                 { src = Ua4; j = i - 147456; dst = (uint2*)g_uh; }
    float4 v = src[j];
    __half2 h01 = __floats2half2_rn(v.x, v.y);
    __half2 h23 = __floats2half2_rn(v.z, v.w);
    uint2 o;
    o.x = *reinterpret_cast<unsigned*>(&h01);
    o.y = *reinterpret_cast<unsigned*>(&h23);
    dst[j] = o;
}

// ---------------- kernel 1: q/k projections via HMMA (R14 proven) ------------
__global__ __launch_bounds__(256) void proj_mma(
    const float* __restrict__ Wb, const float* __restrict__ Ub)
{
    __shared__ __half As[2][128][40];
    __shared__ __half Bs[2][64][40];

    const __half* A    = g_xh;
    const __half* Bw   = blockIdx.z ? g_uh : g_wh;
    const float*  bias = blockIdx.z ? Ub : Wb;
    __half*       out  = blockIdx.z ? g_k : g_q;

    const int bn = blockIdx.x * 64;
    const int bm = blockIdx.y * 128;
    const int tid = threadIdx.x, warp = tid >> 5, lane = tid & 31;
    const int wm = warp >> 1, wn = warp & 1;
    const int gq = lane >> 2, tq = lane & 3;

    const int ar0 = tid >> 2, aq = tid & 3;
    const int br  = tid >> 2, bq = tid & 3;

    float acc[2][4][4] = {};

    cp16(&As[0][ar0][aq * 8],      &A[(bm + ar0) * DD + aq * 8]);
    cp16(&As[0][ar0 + 64][aq * 8], &A[(bm + ar0 + 64) * DD + aq * 8]);
    cp16(&Bs[0][br][bq * 8],       &Bw[(bn + br) * DD + bq * 8]);
    CP_COMMIT();

    #pragma unroll
    for (int it = 0; it < 8; it++) {
        CP_WAIT0();
        __syncthreads();
        if (it < 7) {
            int nk = (it + 1) * 32, s = (it + 1) & 1;
            cp16(&As[s][ar0][aq * 8],      &A[(bm + ar0) * DD + nk + aq * 8]);
            cp16(&As[s][ar0 + 64][aq * 8], &A[(bm + ar0 + 64) * DD + nk + aq * 8]);
            cp16(&Bs[s][br][bq * 8],       &Bw[(bn + br) * DD + nk + bq * 8]);
            CP_COMMIT();
        }
        const int cur = it & 1;

        #pragma unroll
        for (int ks = 0; ks < 2; ks++) {
            int kc = ks * 16;
            unsigned a[2][4], bf[2][4];
            #pragma unroll
            for (int tm = 0; tm < 2; tm++) {
                int r = wm * 32 + tm * 16 + (lane & 15);
                int c = kc + 8 * (lane >> 4);
                ldsm_x4(a[tm], &As[cur][r][c]);
            }
            #pragma unroll
            for (int tn = 0; tn < 2; tn++) {
                int r = wn * 32 + tn * 16 + (lane & 7) + 8 * (lane >> 4);
                int c = kc + 8 * ((lane >> 3) & 1);
                ldsm_x4(bf[tn], &Bs[cur][r][c]);
            }
            #pragma unroll
            for (int tm = 0; tm < 2; tm++)
                #pragma unroll
                for (int tn8 = 0; tn8 < 4; tn8++)
                    mma16816(acc[tm][tn8], a[tm],
                             bf[tn8 >> 1][(tn8 & 1) * 2],
                             bf[tn8 >> 1][(tn8 & 1) * 2 + 1]);
        }
    }

    #pragma unroll
    for (int tm = 0; tm < 2; tm++) {
        #pragma unroll
        for (int tn8 = 0; tn8 < 4; tn8++) {
            int c = bn + wn * 32 + tn8 * 8 + 2 * tq;
            float2 bv = *(const float2*)&bias[c];
            int r0 = bm + wm * 32 + tm * 16 + gq;
            __half2 h0 = __floats2half2_rn(acc[tm][tn8][0] + bv.x,
                                           acc[tm][tn8][1] + bv.y);
            __half2 h1 = __floats2half2_rn(acc[tm][tn8][2] + bv.x,
                                           acc[tm][tn8][3] + bv.y);
            *(__half2*)&out[r0 * DD + c] = h0;
            *(__half2*)&out[(r0 + 8) * DD + c] = h1;
        }
    }
}

// ---------------- kernel 2: additive-attention scores (R14 proven) ----------
#define KT 32
#define QB 64
#define QSTAGE 32

__global__ __launch_bounds__(256, 3) void score_kernel(const float* __restrict__ Va)
{
    __shared__ __align__(16) unsigned q_sh[QSTAGE][320];  // 40 KB

    const int tid  = threadIdx.x;
    const int w    = tid >> 5;
    const int lane = tid & 31;
    const int dg   = lane >> 2;
    const int kis  = lane & 3;

    const int b     = blockIdx.z;
    const int k0    = blockIdx.x * KT;
    const int qbase = blockIdx.y * QB;
    const int krow  = k0 + w * 4 + kis;

    unsigned kreg[16];
    {
        const uint4* kp = reinterpret_cast<const uint4*>(
            g_k + ((b * NN + krow) << 8) + dg * 32);
        #pragma unroll
        for (int j = 0; j < 4; j++) {
            uint4 t = kp[j];
            kreg[4*j+0] = t.x; kreg[4*j+1] = t.y;
            kreg[4*j+2] = t.z; kreg[4*j+3] = t.w;
        }
    }
    unsigned vh[16];
    {
        const float4* vp = reinterpret_cast<const float4*>(Va + dg * 32);
        #pragma unroll
        for (int j = 0; j < 8; j++) {
            float4 v = vp[j];
            __half2 a = __floats2half2_rn(v.x, v.y);
            __half2 c = __floats2half2_rn(v.z, v.w);
            vh[2*j]   = *reinterpret_cast<unsigned*>(&a);
            vh[2*j+1] = *reinterpret_cast<unsigned*>(&c);
        }
    }

    for (int qc = 0; qc < QB; qc += QSTAGE) {
        __syncthreads();
        const uint4* gq4 = reinterpret_cast<const uint4*>(
            g_q + ((b * NN + qbase + qc) << 8));
        #pragma unroll
        for (int l = 0; l < 4; l++) {
            int idx = tid + 256 * l;
            int r  = idx >> 5;
            int p4 = idx & 31;
            uint4 v = gq4[(r << 5) + p4];
            *reinterpret_cast<uint4*>(&q_sh[r][(p4 >> 2) * 40 + (p4 & 3) * 4]) = v;
        }
        __syncthreads();

        #pragma unroll 2
        for (int qi = 0; qi < QSTAGE; qi++) {
            const uint4* q4 = reinterpret_cast<const uint4*>(&q_sh[qi][dg * 40]);
            unsigned hacc[4] = {0u, 0u, 0u, 0u};
            #pragma unroll
            for (int j = 0; j < 4; j++) {
                uint4 qv = q4[j];
                unsigned qh[4] = {qv.x, qv.y, qv.z, qv.w};
                #pragma unroll
                for (int u = 0; u < 4; u++) {
                    int i = 4 * j + u;
                    unsigned t = tanh_h2(hadd2_u(qh[u], kreg[i]));
                    hacc[u] = hfma2_u(t, vh[i], hacc[u]);
                }
            }
            float2 f0 = __half22float2(*reinterpret_cast<__half2*>(&hacc[0]));
            float2 f1 = __half22float2(*reinterpret_cast<__half2*>(&hacc[1]));
            float2 f2 = __half22float2(*reinterpret_cast<__half2*>(&hacc[2]));
            float2 f3 = __half22float2(*reinterpret_cast<__half2*>(&hacc[3]));
            float partial = ((f0.x + f0.y) + (f1.x + f1.y))
                          + ((f2.x + f2.y) + (f3.x + f3.y));
            partial += __shfl_xor_sync(0xffffffffu, partial, 16);
            partial += __shfl_xor_sync(0xffffffffu, partial, 8);
            partial += __shfl_xor_sync(0xffffffffu, partial, 4);
            if (dg == 0) {
                g_wei[((b * NN + qbase + qc + qi) << 9) + krow] = partial;
            }
        }
    }
}

// ---------------- kernel 3: masked softmax -> fp16 weights (4 rows/block) ---
__global__ __launch_bounds__(512) void softmax_kernel(const int* __restrict__ mask)
{
    const int sub = threadIdx.x >> 7;
    const int t   = threadIdx.x & 127;
    const int row = blockIdx.x * 4 + sub;
    const float* wrow = g_wei + row * NN;
    const int* mrow = mask + row * NN;
    __shared__ float red[4][4];

    float4 v = reinterpret_cast<const float4*>(wrow)[t];
    int4   m = reinterpret_cast<const int4*>(mrow)[t];
    if (m.x == 0) v.x = -1e30f;
    if (m.y == 0) v.y = -1e30f;
    if (m.z == 0) v.z = -1e30f;
    if (m.w == 0) v.w = -1e30f;

    float mx = fmaxf(fmaxf(v.x, v.y), fmaxf(v.z, v.w));
    #pragma unroll
    for (int s = 16; s > 0; s >>= 1) mx = fmaxf(mx, __shfl_xor_sync(0xffffffffu, mx, s));
    if ((t & 31) == 0) red[sub][t >> 5] = mx;
    __syncthreads();
    mx = fmaxf(fmaxf(red[sub][0], red[sub][1]), fmaxf(red[sub][2], red[sub][3]));
    __syncthreads();

    v.x = __expf(v.x - mx); v.y = __expf(v.y - mx);
    v.z = __expf(v.z - mx); v.w = __expf(v.w - mx);
    float sum = (v.x + v.y) + (v.z + v.w);
    #pragma unroll
    for (int s = 16; s > 0; s >>= 1) sum += __shfl_xor_sync(0xffffffffu, sum, s);
    if ((t & 31) == 0) red[sub][t >> 5] = sum;
    __syncthreads();
    sum = (red[sub][0] + red[sub][1]) + (red[sub][2] + red[sub][3]);
    float inv = 1.0f / sum;

    __half2 h01 = __floats2half2_rn(v.x * inv, v.y * inv);
    __half2 h23 = __floats2half2_rn(v.z * inv, v.w * inv);
    uint2 o;
    o.x = *reinterpret_cast<unsigned*>(&h01);
    o.y = *reinterpret_cast<unsigned*>(&h23);
    reinterpret_cast<uint2*>(g_weih + row * NN)[t] = o;
}

// ---------------- kernel 4: out = wei @ X via HMMA ---------------------------
// BM=32, BN=64 -> grid (4, 16, 4) = 256 blocks (2 CTAs/SM) for latency hiding.
// 3-stage cp.async pipeline with wait_group 1: waited group was committed two
// iterations earlier -> L2 latency fully hidden.
__global__ __launch_bounds__(256) void av_mma(float* __restrict__ out)
{
    __shared__ __half As[3][32][40];
    __shared__ __half Bs[3][32][72];

    const int b  = blockIdx.z;
    const int bn = blockIdx.x * 64;   // d
    const int bm = blockIdx.y * 32;   // q
    const __half* A  = g_weih + b * NN * NN;
    const __half* Bx = g_xh + b * NN * DD;

    const int tid = threadIdx.x, warp = tid >> 5, lane = tid & 31;
    const int wm = warp >> 2, wn = warp & 3;   // warp tile 16x16 (2x4 warps)
    const int gq = lane >> 2, tq = lane & 3;

    const int ar = tid >> 2, aq = tid & 3;    // tid<128: A 32 rows x 4 quads
    const int br = tid >> 3, bq = tid & 7;    // all: B 32 rows x 8 quads

    float acc[2][4] = {};   // [tn8][4]

    // prologue: stages 0 and 1 as separate commit groups
    #pragma unroll
    for (int s = 0; s < 2; s++) {
        if (tid < 128)
            cp16(&As[s][ar][aq * 8], &A[(bm + ar) * NN + s * 32 + aq * 8]);
        cp16(&Bs[s][br][bq * 8], &Bx[(s * 32 + br) * DD + bn + bq * 8]);
        CP_COMMIT();
    }

    int cur = 0;
    #pragma unroll 1
    for (int it = 0; it < 16; it++) {
        CP_WAIT1();            // stage `it` ready (committed >=2 iters ago)
        __syncthreads();
        if (it < 14) {
            int nk = (it + 2) * 32;
            int s  = (it + 2) % 3;
            if (tid < 128)
                cp16(&As[s][ar][aq * 8], &A[(bm + ar) * NN + nk + aq * 8]);
            cp16(&Bs[s][br][bq * 8], &Bx[(nk + br) * DD + bn + bq * 8]);
            CP_COMMIT();
        }

        #pragma unroll
        for (int ks = 0; ks < 2; ks++) {
            int kc = ks * 16;
            unsigned a[4], bf[4];
            {
                int r = wm * 16 + (lane & 15);
                int c = kc + 8 * (lane >> 4);
                ldsm_x4(a, &As[cur][r][c]);
            }
            {
                int kr = kc + (lane & 7) + 8 * ((lane >> 3) & 1);
                int nc = wn * 16 + 8 * (lane >> 4);
                ldsm_x4_trans(bf, &Bs[cur][kr][nc]);
            }
            #pragma unroll
            for (int tn8 = 0; tn8 < 2; tn8++)
                mma16816(acc[tn8], a, bf[tn8 * 2], bf[tn8 * 2 + 1]);
        }
        cur = (cur + 1) % 3;
        __syncthreads();       // compute done before this stage is refilled
    }

    #pragma unroll
    for (int tn8 = 0; tn8 < 2; tn8++) {
        int c  = bn + wn * 16 + tn8 * 8 + 2 * tq;
        int r0 = bm + wm * 16 + gq;
        *(float2*)&out[(b * NN + r0) * DD + c] =
            make_float2(acc[tn8][0], acc[tn8][1]);
        *(float2*)&out[(b * NN + r0 + 8) * DD + c] =
            make_float2(acc[tn8][2], acc[tn8][3]);
    }
}

// ---------------- launcher ---------------------------------------------------
extern "C" void kernel_launch(void* const* d_in, const int* in_sizes, int n_in,
                              void* d_out, int out_size)
{
    const float* X    = (const float*)d_in[0];  // [4,512,256]
    const int*   mask = (const int*)  d_in[1];  // [4,512,512]
    const float* Wa_w = (const float*)d_in[2];  // [256,256]
    const float* Wa_b = (const float*)d_in[3];  // [256]
    const float* Ua_w = (const float*)d_in[4];  // [256,256]
    const float* Ua_b = (const float*)d_in[5];  // [256]
    const float* Va_w = (const float*)d_in[6];  // [1,256]
    // d_in[7] = Va_b : softmax-invariant constant -> unused

    (void)in_sizes; (void)n_in; (void)out_size;

    conv_kernel<<<640, 256>>>((const float4*)X, (const float4*)Wa_w,
                              (const float4*)Ua_w);

    dim3 pgrid(DD / 64, (BB * NN) / 128, 2);    // 128 blocks
    proj_mma<<<pgrid, 256>>>(Wa_b, Ua_b);

    dim3 sgrid(NN / KT, NN / QB, BB);           // 512 blocks
    score_kernel<<<sgrid, 256>>>(Va_w);

    softmax_kernel<<<512, 512>>>(mask);

    dim3 agrid(DD / 64, NN / 32, BB);           // 4 x 16 x 4 = 256 blocks
    av_mma<<<agrid, 256>>>((float*)d_out);
}